// round 16
// baseline (speedup 1.0000x reference)
#include <cuda_runtime.h>
#include <cuda_bf16.h>
#include <float.h>
#include <cstdint>

#define N_ROWS 32768
#define NUMC   4096
#define DIM    512
#define NCH    64                     // codes per block (CTA n-tile)
#define NQ     4                      // code-range quarters
#define QCODES (NUMC / NQ)            // 1024 codes per quarter
#define NCHQ   ((QCODES / NCH) * 8)   // 16 code blocks x 8 k-chunks = 128 per CTA

#define TILE_A  (128 * 144)           // A tile: 128 rows x 144B pitch
#define TILE_B  (64 * 144)            // B tile: 64 rows x 144B pitch
#define STAGE_S (TILE_A + TILE_B)     // 27648 B
#define SMEM_TOTAL (512 + 2 * STAGE_S)  // 55808 B -> 3 CTAs/SM

#define NKEEP 3                       // top-3 per (quarter, 32-col half)
#define NCAND (NQ * 2 * NKEEP)        // 24 candidates per row
#define DELTA 1.0f                    // exact-rescore window (~10 sigma of bf16 noise)

// ---- scratch (device globals; no runtime allocation allowed) ----
__device__ __nv_bfloat16 g_xb[N_ROWS * DIM];
__device__ __nv_bfloat16 g_wb[NUMC * DIM];
__device__ float g_z2[NUMC];
__device__ int   g_cand[N_ROWS * NCAND];
__device__ float g_cval[N_ROWS * NCAND];
__device__ float g_rowloss[N_ROWS];

// ================= helpers =================
__device__ __forceinline__ uint32_t smem_u32(const void* p) {
    uint32_t a;
    asm("{ .reg .u64 t; cvta.to.shared.u64 t, %1; cvt.u32.u64 %0, t; }" : "=r"(a) : "l"(p));
    return a;
}
__device__ __forceinline__ void cp16(uint32_t s, const void* g) {
    asm volatile("cp.async.cg.shared.global [%0], [%1], 16;" :: "r"(s), "l"(g));
}
#define CP_COMMIT() asm volatile("cp.async.commit_group;" ::: "memory")
#define CP_WAIT1()  asm volatile("cp.async.wait_group 1;" ::: "memory")
#define CP_WAIT0()  asm volatile("cp.async.wait_group 0;" ::: "memory")
#define LDSM4(r0, r1, r2, r3, a) \
    asm volatile("ldmatrix.sync.aligned.m8n8.x4.shared.b16 {%0,%1,%2,%3}, [%4];" \
        : "=r"(r0), "=r"(r1), "=r"(r2), "=r"(r3) : "r"(a))

__device__ __forceinline__ void mma16816(float* c, const uint32_t* a,
                                         uint32_t b0, uint32_t b1) {
    asm("mma.sync.aligned.m16n8k16.row.col.f32.bf16.bf16.f32 "
        "{%0,%1,%2,%3}, {%4,%5,%6,%7}, {%8,%9}, {%0,%1,%2,%3};"
        : "+f"(c[0]), "+f"(c[1]), "+f"(c[2]), "+f"(c[3])
        : "r"(a[0]), "r"(a[1]), "r"(a[2]), "r"(a[3]), "r"(b0), "r"(b1));
}

// running top-3 insert (ascending-index scan; strict < keeps lowest idx on ties)
__device__ __forceinline__ void ins3(float t, int idx, float* v, int* ix) {
    if (t < v[2]) {
        if (t < v[1]) {
            v[2] = v[1]; ix[2] = ix[1];
            if (t < v[0]) { v[1] = v[0]; ix[1] = ix[0]; v[0] = t; ix[0] = idx; }
            else          { v[1] = t; ix[1] = idx; }
        } else {
            v[2] = t; ix[2] = idx;
        }
    }
}
// tie-aware insert for cross-lane merge
__device__ __forceinline__ void ins3tie(float t, int idx, float* v, int* ix) {
    bool lt2 = (t < v[2]) || (t == v[2] && idx < ix[2]);
    if (lt2) {
        bool lt1 = (t < v[1]) || (t == v[1] && idx < ix[1]);
        if (lt1) {
            v[2] = v[1]; ix[2] = ix[1];
            bool lt0 = (t < v[0]) || (t == v[0] && idx < ix[0]);
            if (lt0) { v[1] = v[0]; ix[1] = ix[0]; v[0] = t; ix[0] = idx; }
            else     { v[1] = t; ix[1] = idx; }
        } else {
            v[2] = t; ix[2] = idx;
        }
    }
}

// ========== kernel 0a: x -> bf16 (vectorized, elementwise) ==========
__global__ void k_split4(const float4* __restrict__ src, int n4) {
    int i = blockIdx.x * blockDim.x + threadIdx.x;
    if (i >= n4) return;
    float4 v = src[i];
    __nv_bfloat162 lo = __floats2bfloat162_rn(v.x, v.y);
    __nv_bfloat162 hi = __floats2bfloat162_rn(v.z, v.w);
    __nv_bfloat162* dst = (__nv_bfloat162*)g_xb;
    dst[i * 2]     = lo;
    dst[i * 2 + 1] = hi;
}

// ====== kernel 0b: e -> bf16 + exact z2 in one pass (warp per code row) ======
__global__ void k_prep_e(const float* __restrict__ e) {
    int w = (blockIdx.x * blockDim.x + threadIdx.x) >> 5;
    int lane = threadIdx.x & 31;
    if (w >= NUMC) return;
    const float4* row = (const float4*)(e + (size_t)w * DIM);
    __nv_bfloat162* dst = (__nv_bfloat162*)(g_wb + (size_t)w * DIM);
    float s = 0.f;
#pragma unroll
    for (int i = 0; i < 4; i++) {
        int p = lane + 32 * i;
        float4 v = row[p];
        s += v.x * v.x + v.y * v.y + v.z * v.z + v.w * v.w;
        dst[p * 2]     = __floats2bfloat162_rn(v.x, v.y);
        dst[p * 2 + 1] = __floats2bfloat162_rn(v.z, v.w);
    }
#pragma unroll
    for (int o = 16; o; o >>= 1) s += __shfl_xor_sync(0xffffffffu, s, o);
    if (lane == 0) g_z2[w] = s;
}

// == kernel 1: bf16 HMMA GEMM, 128x64 CTA tile, 3 CTAs/SM (24 warps) ==
__device__ __forceinline__ void prefetch_chunk(uint32_t st, int ci, int qbase,
                                               int rowBase, int tid) {
    int cb = qbase + ((ci >> 3) * NCH);
    int kc = ci & 7;
    // A tile: 128 rows x 8 c16-segs = 1024 segs, 4 per thread
#pragma unroll
    for (int j = 0; j < 4; j++) {
        int seg = tid + j * 256;
        int r = seg >> 3, c16 = seg & 7;
        uint32_t so = (uint32_t)(r * 144 + c16 * 16);
        size_t gA = (size_t)(rowBase + r) * DIM + kc * 64 + c16 * 8;
        cp16(st + so, g_xb + gA);
    }
    // B tile: 64 rows x 8 c16-segs = 512 segs, 2 per thread
#pragma unroll
    for (int j = 0; j < 2; j++) {
        int seg = tid + j * 256;
        int r = seg >> 3, c16 = seg & 7;
        uint32_t so = (uint32_t)(r * 144 + c16 * 16);
        size_t gB = (size_t)(cb + r) * DIM + kc * 64 + c16 * 8;
        cp16(st + TILE_A + so, g_wb + gB);
    }
    CP_COMMIT();
}

__global__ __launch_bounds__(256, 3) void k_mma() {
    extern __shared__ char smem[];
    float* z2s = (float*)smem;                       // 64 floats used (512 B reserved)
    const uint32_t sb = smem_u32(smem) + 512;        // stage area, 16B aligned
    const int tid = threadIdx.x;
    const int lane = tid & 31;
    const int wid = tid >> 5;
    const int m0 = (wid >> 1) * 32;                  // warp row origin: 0/32/64/96
    const int n0 = (wid & 1) * 32;                   // warp col origin: 0/32
    const int rowBase = blockIdx.y * 128;
    const int qid = blockIdx.x;
    const int qbase = qid * QCODES;

    // ldmatrix lane-relative byte offsets (144 B row pitch)
    const uint32_t a_off = (uint32_t)((lane & 15) * 144 + (lane >> 4) * 16);
    const uint32_t b_off = (uint32_t)((((lane & 7) + ((lane >> 4) << 3)) * 144) +
                                      (((lane >> 3) & 1) * 16));

    float acc[2][4][4];                              // [m16-tile][n8-tile][frag]
    float v[4][NKEEP];  int ix[4][NKEEP];            // top-3 per row-slot (this 32-half)
#pragma unroll
    for (int s = 0; s < 4; s++)
#pragma unroll
        for (int c = 0; c < NKEEP; c++) { v[s][c] = FLT_MAX; ix[s][c] = 0; }

    prefetch_chunk(sb, 0, qbase, rowBase, tid);

    for (int ci = 0; ci < NCHQ; ci++) {
        const int cb = qbase + ((ci >> 3) * NCH);
        const int kc = ci & 7;
        if (kc == 0) {
#pragma unroll
            for (int mt = 0; mt < 2; mt++)
#pragma unroll
                for (int nt = 0; nt < 4; nt++)
#pragma unroll
                    for (int c = 0; c < 4; c++) acc[mt][nt][c] = 0.f;
            if (tid < NCH) z2s[tid] = g_z2[cb + tid];
        }

        if (ci + 1 < NCHQ) {
            prefetch_chunk(sb + ((ci + 1) & 1) * STAGE_S, ci + 1, qbase, rowBase, tid);
            CP_WAIT1();
        } else {
            CP_WAIT0();
        }
        __syncthreads();

        const uint32_t st = sb + (ci & 1) * STAGE_S;
        const uint32_t sA = st, sB = st + TILE_A;

#pragma unroll
        for (int ks = 0; ks < 4; ks++) {
            const uint32_t kb = (uint32_t)(ks * 32);
            uint32_t ah[2][4];
            LDSM4(ah[0][0], ah[0][1], ah[0][2], ah[0][3], sA + (uint32_t)(m0 * 144) + a_off + kb);
            LDSM4(ah[1][0], ah[1][1], ah[1][2], ah[1][3], sA + (uint32_t)((m0 + 16) * 144) + a_off + kb);
#pragma unroll
            for (int p = 0; p < 2; p++) {
                uint32_t bh[4];
                LDSM4(bh[0], bh[1], bh[2], bh[3], sB + (uint32_t)((n0 + 16 * p) * 144) + b_off + kb);
#pragma unroll
                for (int mt = 0; mt < 2; mt++) {
                    mma16816(acc[mt][2 * p],     ah[mt], bh[0], bh[1]);
                    mma16816(acc[mt][2 * p + 1], ah[mt], bh[2], bh[3]);
                }
            }
        }

        if (kc == 7) {
            // epilogue: rank z2 - 2*xz, running top-3 per row-slot
#pragma unroll
            for (int mt = 0; mt < 2; mt++)
#pragma unroll
                for (int nt = 0; nt < 4; nt++) {
                    int nl = n0 + nt * 8 + (lane & 3) * 2;
                    float z0 = z2s[nl], z1 = z2s[nl + 1];
                    int g0 = cb + nl;
                    ins3(z0 - 2.f * acc[mt][nt][0], g0,     v[mt * 2],     ix[mt * 2]);
                    ins3(z1 - 2.f * acc[mt][nt][1], g0 + 1, v[mt * 2],     ix[mt * 2]);
                    ins3(z0 - 2.f * acc[mt][nt][2], g0,     v[mt * 2 + 1], ix[mt * 2 + 1]);
                    ins3(z1 - 2.f * acc[mt][nt][3], g0 + 1, v[mt * 2 + 1], ix[mt * 2 + 1]);
                }
        }
        __syncthreads();
    }

    // merge top-3 across the 4 lanes (lane%4) sharing each row; tie -> lowest index
#pragma unroll
    for (int s = 0; s < 4; s++) {
#pragma unroll
        for (int step = 1; step <= 2; step <<= 1) {
            float ov[NKEEP]; int oi[NKEEP];
#pragma unroll
            for (int c = 0; c < NKEEP; c++) {
                ov[c] = __shfl_xor_sync(0xffffffffu, v[s][c], step);
                oi[c] = __shfl_xor_sync(0xffffffffu, ix[s][c], step);
            }
#pragma unroll
            for (int c = 0; c < NKEEP; c++) ins3tie(ov[c], oi[c], v[s], ix[s]);
        }
    }
    // disjoint slots: quarter qid, 32-col half (wid&1)
    if ((lane & 3) == 0) {
#pragma unroll
        for (int s = 0; s < 4; s++) {
            int mt = s >> 1, h = s & 1;
            int row = rowBase + m0 + mt * 16 + h * 8 + (lane >> 2);
            int base = row * NCAND + qid * (2 * NKEEP) + (wid & 1) * NKEEP;
#pragma unroll
            for (int c = 0; c < NKEEP; c++) {
                g_cand[base + c] = ix[s][c];
                g_cval[base + c] = v[s][c];
            }
        }
    }
}

// ===== kernel 2: delta-window exact rescore + gather + per-row loss =====
__global__ void k_finish(const float* __restrict__ x, const float* __restrict__ e,
                         float* __restrict__ out) {
    int r = (blockIdx.x * blockDim.x + threadIdx.x) >> 5;
    int lane = threadIdx.x & 31;
    if (r >= N_ROWS) return;

    float cval = FLT_MAX;
    int   cidx = 0;
    if (lane < NCAND) {
        cval = g_cval[r * NCAND + lane];
        cidx = g_cand[r * NCAND + lane];
    }
    float mn = cval;
#pragma unroll
    for (int o = 16; o; o >>= 1) mn = fminf(mn, __shfl_xor_sync(0xffffffffu, mn, o));
    const float thresh = mn + DELTA;

    const float4* xr = (const float4*)(x + (size_t)r * DIM);
    float4 xv[4];
    float x2p = 0.f;
#pragma unroll
    for (int i = 0; i < 4; i++) {
        xv[i] = xr[lane + 32 * i];
        x2p += xv[i].x * xv[i].x + xv[i].y * xv[i].y + xv[i].z * xv[i].z + xv[i].w * xv[i].w;
    }
#pragma unroll
    for (int o = 16; o; o >>= 1) x2p += __shfl_xor_sync(0xffffffffu, x2p, o);

    float bestd = FLT_MAX;
    int   besti = 0x7fffffff;
    for (int c = 0; c < NCAND; c++) {
        float vc = __shfl_sync(0xffffffffu, cval, c);
        if (vc > thresh) continue;               // outside window: cannot be exact min
        int idx = __shfl_sync(0xffffffffu, cidx, c);
        const float4* zr = (const float4*)(e + (size_t)idx * DIM);
        float xzp = 0.f, z2p = 0.f;
#pragma unroll
        for (int i = 0; i < 4; i++) {
            float4 z = zr[lane + 32 * i];
            xzp += xv[i].x * z.x + xv[i].y * z.y + xv[i].z * z.z + xv[i].w * z.w;
            z2p += z.x * z.x + z.y * z.y + z.z * z.z + z.w * z.w;
        }
#pragma unroll
        for (int o = 16; o; o >>= 1) {
            xzp += __shfl_xor_sync(0xffffffffu, xzp, o);
            z2p += __shfl_xor_sync(0xffffffffu, z2p, o);
        }
        float d = __fsub_rn(__fadd_rn(x2p, z2p), __fmul_rn(2.0f, xzp));
        if (d < bestd || (d == bestd && idx < besti)) { bestd = d; besti = idx; }
    }

    const float4* zr = (const float4*)(e + (size_t)besti * DIM);
    float4* orow = (float4*)(out + (size_t)r * DIM);
    float s = 0.f;
#pragma unroll
    for (int i = 0; i < 4; i++) {
        float4 z = zr[lane + 32 * i];
        orow[lane + 32 * i] = z;
        float dx = xv[i].x - z.x, dy = xv[i].y - z.y;
        float dz = xv[i].z - z.z, dw = xv[i].w - z.w;
        s += dx * dx + dy * dy + dz * dz + dw * dw;
    }
#pragma unroll
    for (int o = 16; o; o >>= 1) s += __shfl_xor_sync(0xffffffffu, s, o);
    if (lane == 0) g_rowloss[r] = s;
}

// ================= kernel 3: deterministic loss reduction =================
__global__ void k_loss(float* __restrict__ out, int out_size) {
    __shared__ float sm[1024];
    int t = threadIdx.x;
    float s = 0.f;
    for (int i = t; i < N_ROWS; i += 1024) s += g_rowloss[i];
    sm[t] = s;
    __syncthreads();
    for (int o = 512; o; o >>= 1) {
        if (t < o) sm[t] += sm[t + o];
        __syncthreads();
    }
    if (t == 0) out[out_size - 1] = sm[0] * 1.25f / (float)((long long)N_ROWS * DIM);
}

extern "C" void kernel_launch(void* const* d_in, const int* in_sizes, int n_in,
                              void* d_out, int out_size) {
    const float* x = (const float*)d_in[0];
    const float* e = (const float*)d_in[1];
    float* out = (float*)d_out;

    cudaFuncSetAttribute(k_mma, cudaFuncAttributeMaxDynamicSharedMemorySize, SMEM_TOTAL);

    k_split4<<<(N_ROWS * DIM / 4) / 256, 256>>>((const float4*)x, N_ROWS * DIM / 4);
    k_prep_e<<<(NUMC * 32) / 256, 256>>>(e);
    dim3 grid(NQ, N_ROWS / 128);
    k_mma<<<grid, 256, SMEM_TOTAL>>>();
    k_finish<<<(N_ROWS * 32) / 256, 256>>>(x, e, out);
    k_loss<<<1, 1024>>>(out, out_size);
}

// round 17
// speedup vs baseline: 1.0511x; 1.0511x over previous
#include <cuda_runtime.h>
#include <cuda_bf16.h>
#include <float.h>
#include <cstdint>

#define N_ROWS 32768
#define NUMC   4096
#define DIM    512
#define NCH    128                    // codes per block
#define NQ     4                      // code-range quarters (one per CTA.x)
#define QCODES (NUMC / NQ)            // 1024 codes per quarter
#define NCHQ   ((QCODES / NCH) * 8)   // 8 code blocks x 8 k-chunks = 64 per CTA

#define ROWPITCH 72                   // bf16 per smem row (144 B) -> conflict-free ldmatrix
#define TILE_S   (128 * ROWPITCH * 2) // 18432 B per operand tile
#define STAGE_S  (2 * TILE_S)         // A, B
#define SMEM_TOTAL (512 + 2 * STAGE_S)

#define NKEEP 3                       // top-3 per (quarter, n-half)
#define NCAND (NQ * 2 * NKEEP)        // 24 candidates per row
#define DELTA 1.0f                    // exact-rescore window (~10 sigma of bf16 noise)

#define NLB 64                        // loss partial blocks

// ---- scratch (device globals; no runtime allocation allowed) ----
__device__ __nv_bfloat16 g_xb[N_ROWS * DIM];
__device__ __nv_bfloat16 g_wb[NUMC * DIM];
__device__ float g_z2[NUMC];
__device__ int   g_cand[N_ROWS * NCAND];
__device__ float g_cval[N_ROWS * NCAND];
__device__ float g_rowloss[N_ROWS];
__device__ float g_partial[NLB];

// ================= helpers =================
__device__ __forceinline__ uint32_t smem_u32(const void* p) {
    uint32_t a;
    asm("{ .reg .u64 t; cvta.to.shared.u64 t, %1; cvt.u32.u64 %0, t; }" : "=r"(a) : "l"(p));
    return a;
}
__device__ __forceinline__ void cp16(uint32_t s, const void* g) {
    asm volatile("cp.async.cg.shared.global [%0], [%1], 16;" :: "r"(s), "l"(g));
}
#define CP_COMMIT() asm volatile("cp.async.commit_group;" ::: "memory")
#define CP_WAIT1()  asm volatile("cp.async.wait_group 1;" ::: "memory")
#define CP_WAIT0()  asm volatile("cp.async.wait_group 0;" ::: "memory")
#define LDSM4(r0, r1, r2, r3, a) \
    asm volatile("ldmatrix.sync.aligned.m8n8.x4.shared.b16 {%0,%1,%2,%3}, [%4];" \
        : "=r"(r0), "=r"(r1), "=r"(r2), "=r"(r3) : "r"(a))

__device__ __forceinline__ void mma16816(float* c, const uint32_t* a,
                                         uint32_t b0, uint32_t b1) {
    asm("mma.sync.aligned.m16n8k16.row.col.f32.bf16.bf16.f32 "
        "{%0,%1,%2,%3}, {%4,%5,%6,%7}, {%8,%9}, {%0,%1,%2,%3};"
        : "+f"(c[0]), "+f"(c[1]), "+f"(c[2]), "+f"(c[3])
        : "r"(a[0]), "r"(a[1]), "r"(a[2]), "r"(a[3]), "r"(b0), "r"(b1));
}

// running top-3 insert (ascending-index scan; strict < keeps lowest idx on ties)
__device__ __forceinline__ void ins3(float t, int idx, float* v, int* ix) {
    if (t < v[2]) {
        if (t < v[1]) {
            v[2] = v[1]; ix[2] = ix[1];
            if (t < v[0]) { v[1] = v[0]; ix[1] = ix[0]; v[0] = t; ix[0] = idx; }
            else          { v[1] = t; ix[1] = idx; }
        } else {
            v[2] = t; ix[2] = idx;
        }
    }
}
// tie-aware insert for cross-lane merge
__device__ __forceinline__ void ins3tie(float t, int idx, float* v, int* ix) {
    bool lt2 = (t < v[2]) || (t == v[2] && idx < ix[2]);
    if (lt2) {
        bool lt1 = (t < v[1]) || (t == v[1] && idx < ix[1]);
        if (lt1) {
            v[2] = v[1]; ix[2] = ix[1];
            bool lt0 = (t < v[0]) || (t == v[0] && idx < ix[0]);
            if (lt0) { v[1] = v[0]; ix[1] = ix[0]; v[0] = t; ix[0] = idx; }
            else     { v[1] = t; ix[1] = idx; }
        } else {
            v[2] = t; ix[2] = idx;
        }
    }
}

// ====== kernel 0: fused prep — blocks [0,16384) split x, [16384,16896) prep e ======
__global__ void k_prep(const float4* __restrict__ x4, const float* __restrict__ e) {
    int b = blockIdx.x;
    if (b < 16384) {
        int i = b * 256 + threadIdx.x;           // n4 = 16384*256 exactly
        float4 v = x4[i];
        __nv_bfloat162* dst = (__nv_bfloat162*)g_xb;
        dst[i * 2]     = __floats2bfloat162_rn(v.x, v.y);
        dst[i * 2 + 1] = __floats2bfloat162_rn(v.z, v.w);
    } else {
        int w = (b - 16384) * 8 + (threadIdx.x >> 5);   // 512 blocks * 8 warps = 4096
        int lane = threadIdx.x & 31;
        const float4* row = (const float4*)(e + (size_t)w * DIM);
        __nv_bfloat162* dst = (__nv_bfloat162*)(g_wb + (size_t)w * DIM);
        float s = 0.f;
#pragma unroll
        for (int i = 0; i < 4; i++) {
            int p = lane + 32 * i;
            float4 v = row[p];
            s += v.x * v.x + v.y * v.y + v.z * v.z + v.w * v.w;   // same form as k_sq
            dst[p * 2]     = __floats2bfloat162_rn(v.x, v.y);
            dst[p * 2 + 1] = __floats2bfloat162_rn(v.z, v.w);
        }
#pragma unroll
        for (int o = 16; o; o >>= 1) s += __shfl_xor_sync(0xffffffffu, s, o);
        if (lane == 0) g_z2[w] = s;
    }
}

// == kernel 1: bf16 HMMA GEMM over ONE code quarter (R15 verbatim) ==
__device__ __forceinline__ void prefetch_chunk(uint32_t st, int ci, int qbase,
                                               int rowBase, int tid) {
    int cb = qbase + ((ci >> 3) << 7);
    int kc = ci & 7;
#pragma unroll
    for (int j = 0; j < 4; j++) {
        int seg = tid + j * 256;                // 0..1023
        int r = seg >> 3, c16 = seg & 7;
        uint32_t so = (uint32_t)(r * 144 + c16 * 16);
        size_t gA = (size_t)(rowBase + r) * DIM + kc * 64 + c16 * 8;
        size_t gB = (size_t)(cb + r) * DIM + kc * 64 + c16 * 8;
        cp16(st + so,          g_xb + gA);
        cp16(st + TILE_S + so, g_wb + gB);
    }
    CP_COMMIT();
}

__global__ __launch_bounds__(256, 2) void k_mma() {
    extern __shared__ char smem[];
    float* z2s = (float*)smem;                       // 128 floats (512 B)
    const uint32_t sb = smem_u32(smem) + 512;        // stage area, 16B aligned
    const int tid = threadIdx.x;
    const int lane = tid & 31;
    const int wid = tid >> 5;
    const int m0 = (wid >> 1) * 32;                  // warp row origin (CTA-rel)
    const int n0 = (wid & 1) * 64;                   // warp col origin
    const int rowBase = blockIdx.y * 128;
    const int qid = blockIdx.x;
    const int qbase = qid * QCODES;

    // ldmatrix lane-relative byte offsets (144 B row pitch)
    const uint32_t a_off = (uint32_t)((lane & 15) * 144 + (lane >> 4) * 16);
    const uint32_t b_off = (uint32_t)((((lane & 7) + ((lane >> 4) << 3)) * 144) +
                                      (((lane >> 3) & 1) * 16));

    float acc[2][8][4];
    float v[4][NKEEP];  int ix[4][NKEEP];            // top-3 per row-slot (this n-half)
#pragma unroll
    for (int s = 0; s < 4; s++)
#pragma unroll
        for (int c = 0; c < NKEEP; c++) { v[s][c] = FLT_MAX; ix[s][c] = 0; }

    prefetch_chunk(sb, 0, qbase, rowBase, tid);

    for (int ci = 0; ci < NCHQ; ci++) {
        const int cb = qbase + ((ci >> 3) << 7);
        const int kc = ci & 7;
        if (kc == 0) {
#pragma unroll
            for (int mt = 0; mt < 2; mt++)
#pragma unroll
                for (int nt = 0; nt < 8; nt++)
#pragma unroll
                    for (int c = 0; c < 4; c++) acc[mt][nt][c] = 0.f;
            if (tid < NCH) z2s[tid] = g_z2[cb + tid];
        }

        if (ci + 1 < NCHQ) {
            prefetch_chunk(sb + ((ci + 1) & 1) * STAGE_S, ci + 1, qbase, rowBase, tid);
            CP_WAIT1();
        } else {
            CP_WAIT0();
        }
        __syncthreads();

        const uint32_t st = sb + (ci & 1) * STAGE_S;
        const uint32_t sA = st, sB = st + TILE_S;

#pragma unroll
        for (int ks = 0; ks < 4; ks++) {
            const uint32_t kb = (uint32_t)(ks * 32);
            uint32_t ah[2][4];
            LDSM4(ah[0][0], ah[0][1], ah[0][2], ah[0][3], sA + (uint32_t)(m0 * 144) + a_off + kb);
            LDSM4(ah[1][0], ah[1][1], ah[1][2], ah[1][3], sA + (uint32_t)((m0 + 16) * 144) + a_off + kb);
#pragma unroll
            for (int p = 0; p < 4; p++) {
                uint32_t bh[4];
                LDSM4(bh[0], bh[1], bh[2], bh[3], sB + (uint32_t)((n0 + 16 * p) * 144) + b_off + kb);
#pragma unroll
                for (int mt = 0; mt < 2; mt++) {
                    mma16816(acc[mt][2 * p],     ah[mt], bh[0], bh[1]);
                    mma16816(acc[mt][2 * p + 1], ah[mt], bh[2], bh[3]);
                }
            }
        }

        if (kc == 7) {
            // epilogue: rank z2 - 2*xz, running top-3 per row-slot
#pragma unroll
            for (int mt = 0; mt < 2; mt++)
#pragma unroll
                for (int nt = 0; nt < 8; nt++) {
                    int nl = n0 + nt * 8 + (lane & 3) * 2;
                    float z0 = z2s[nl], z1 = z2s[nl + 1];
                    int g0 = cb + nl;
                    ins3(z0 - 2.f * acc[mt][nt][0], g0,     v[mt * 2],     ix[mt * 2]);
                    ins3(z1 - 2.f * acc[mt][nt][1], g0 + 1, v[mt * 2],     ix[mt * 2]);
                    ins3(z0 - 2.f * acc[mt][nt][2], g0,     v[mt * 2 + 1], ix[mt * 2 + 1]);
                    ins3(z1 - 2.f * acc[mt][nt][3], g0 + 1, v[mt * 2 + 1], ix[mt * 2 + 1]);
                }
        }
        __syncthreads();
    }

    // merge top-3 across the 4 lanes (lane%4) sharing each row; tie -> lowest index
#pragma unroll
    for (int s = 0; s < 4; s++) {
#pragma unroll
        for (int step = 1; step <= 2; step <<= 1) {
            float ov[NKEEP]; int oi[NKEEP];
#pragma unroll
            for (int c = 0; c < NKEEP; c++) {
                ov[c] = __shfl_xor_sync(0xffffffffu, v[s][c], step);
                oi[c] = __shfl_xor_sync(0xffffffffu, ix[s][c], step);
            }
#pragma unroll
            for (int c = 0; c < NKEEP; c++) ins3tie(ov[c], oi[c], v[s], ix[s]);
        }
    }
    // disjoint slots: quarter qid, n-half (wid&1)
    if ((lane & 3) == 0) {
#pragma unroll
        for (int s = 0; s < 4; s++) {
            int mt = s >> 1, h = s & 1;
            int row = rowBase + m0 + mt * 16 + h * 8 + (lane >> 2);
            int base = row * NCAND + qid * (2 * NKEEP) + (wid & 1) * NKEEP;
#pragma unroll
            for (int c = 0; c < NKEEP; c++) {
                g_cand[base + c] = ix[s][c];
                g_cval[base + c] = v[s][c];
            }
        }
    }
}

// ===== kernel 2: delta-window exact rescore + gather + per-row loss =====
__global__ void k_finish(const float* __restrict__ x, const float* __restrict__ e,
                         float* __restrict__ out) {
    int r = (blockIdx.x * blockDim.x + threadIdx.x) >> 5;
    int lane = threadIdx.x & 31;
    if (r >= N_ROWS) return;

    // load candidate (approx val, idx) pairs; lanes >= NCAND hold +inf
    float cval = FLT_MAX;
    int   cidx = 0;
    if (lane < NCAND) {
        cval = g_cval[r * NCAND + lane];
        cidx = g_cand[r * NCAND + lane];
    }
    float mn = cval;
#pragma unroll
    for (int o = 16; o; o >>= 1) mn = fminf(mn, __shfl_xor_sync(0xffffffffu, mn, o));
    const float thresh = mn + DELTA;

    const float4* xr = (const float4*)(x + (size_t)r * DIM);
    float4 xv[4];
    float x2p = 0.f;
#pragma unroll
    for (int i = 0; i < 4; i++) {
        xv[i] = xr[lane + 32 * i];
        x2p += xv[i].x * xv[i].x + xv[i].y * xv[i].y + xv[i].z * xv[i].z + xv[i].w * xv[i].w;
    }
#pragma unroll
    for (int o = 16; o; o >>= 1) x2p += __shfl_xor_sync(0xffffffffu, x2p, o);

    float bestd = FLT_MAX;
    int   besti = 0x7fffffff;
    for (int c = 0; c < NCAND; c++) {
        float vc = __shfl_sync(0xffffffffu, cval, c);
        if (vc > thresh) continue;               // outside window: cannot be exact min
        int idx = __shfl_sync(0xffffffffu, cidx, c);
        const float4* zr = (const float4*)(e + (size_t)idx * DIM);
        float xzp = 0.f, z2p = 0.f;
#pragma unroll
        for (int i = 0; i < 4; i++) {
            float4 z = zr[lane + 32 * i];
            xzp += xv[i].x * z.x + xv[i].y * z.y + xv[i].z * z.z + xv[i].w * z.w;
            z2p += z.x * z.x + z.y * z.y + z.z * z.z + z.w * z.w;
        }
#pragma unroll
        for (int o = 16; o; o >>= 1) {
            xzp += __shfl_xor_sync(0xffffffffu, xzp, o);
            z2p += __shfl_xor_sync(0xffffffffu, z2p, o);
        }
        float d = __fsub_rn(__fadd_rn(x2p, z2p), __fmul_rn(2.0f, xzp));
        if (d < bestd || (d == bestd && idx < besti)) { bestd = d; besti = idx; }
    }

    const float4* zr = (const float4*)(e + (size_t)besti * DIM);
    float4* orow = (float4*)(out + (size_t)r * DIM);
    float s = 0.f;
#pragma unroll
    for (int i = 0; i < 4; i++) {
        float4 z = zr[lane + 32 * i];
        orow[lane + 32 * i] = z;
        float dx = xv[i].x - z.x, dy = xv[i].y - z.y;
        float dz = xv[i].z - z.z, dw = xv[i].w - z.w;
        s += dx * dx + dy * dy + dz * dz + dw * dw;
    }
#pragma unroll
    for (int o = 16; o; o >>= 1) s += __shfl_xor_sync(0xffffffffu, s, o);
    if (lane == 0) g_rowloss[r] = s;
}

// ============ kernel 3a: per-block loss partials (deterministic) ============
__global__ void k_loss1() {
    __shared__ float sm[512];
    int t = threadIdx.x;
    int base = blockIdx.x * (N_ROWS / NLB);          // 512 rows per block
    float s = 0.f;
    s += g_rowloss[base + t];                        // fixed-order: exactly 1 each
    sm[t] = s;
    __syncthreads();
    for (int o = 256; o; o >>= 1) {
        if (t < o) sm[t] += sm[t + o];
        __syncthreads();
    }
    if (t == 0) g_partial[blockIdx.x] = sm[0];
}

// ============ kernel 3b: fold partials, write loss ============
__global__ void k_loss2(float* __restrict__ out, int out_size) {
    if (threadIdx.x == 0) {
        float s = 0.f;
        for (int i = 0; i < NLB; i++) s += g_partial[i];
        out[out_size - 1] = s * 1.25f / (float)((long long)N_ROWS * DIM);
    }
}

extern "C" void kernel_launch(void* const* d_in, const int* in_sizes, int n_in,
                              void* d_out, int out_size) {
    const float* x = (const float*)d_in[0];
    const float* e = (const float*)d_in[1];
    float* out = (float*)d_out;

    cudaFuncSetAttribute(k_mma, cudaFuncAttributeMaxDynamicSharedMemorySize, SMEM_TOTAL);

    k_prep<<<16384 + 512, 256>>>((const float4*)x, e);
    dim3 grid(NQ, N_ROWS / 128);
    k_mma<<<grid, 256, SMEM_TOTAL>>>();
    k_finish<<<(N_ROWS * 32) / 256, 256>>>(x, e, out);
    k_loss1<<<NLB, 512>>>();
    k_loss2<<<1, 32>>>(out, out_size);
}